// round 3
// baseline (speedup 1.0000x reference)
#include <cuda_runtime.h>
#include <cstdint>

#define NN 50000
#define EE 800000
#define HH 128
#define RR 8
#define MT 128                       // dst rows per block
#define NBLK ((NN + MT - 1) / MT)    // 391
#define SROW 132                     // padded s-tile row stride (floats)
#define SMEM_BYTES ((MT * SROW + HH * HH) * 4)

// ---------------- scratch (device globals; no allocation allowed) ----------------
__device__ float g_hA[(size_t)NN * HH];
__device__ float g_hB[(size_t)NN * HH];
__device__ int   g_cnt[NN * RR];
__device__ float g_invc[NN * RR];
__device__ int   g_rowptr[NN + 1];
__device__ int   g_beg[NN * RR];
__device__ int   g_cur[NN * RR];
__device__ int   g_ep[EE];           // src node id, CSR-sorted by (dst, etype)
__device__ float g_u[2 * HH];        // column sums of final layer (per graph)

// ---------------- f32x2 packed-FMA helpers ----------------
__device__ __forceinline__ unsigned long long pk2(float lo, float hi) {
    unsigned long long r;
    asm("mov.b64 %0, {%1, %2};" : "=l"(r) : "f"(lo), "f"(hi));
    return r;
}
__device__ __forceinline__ void upk2(unsigned long long v, float& lo, float& hi) {
    asm("mov.b64 {%0, %1}, %2;" : "=f"(lo), "=f"(hi) : "l"(v));
}
__device__ __forceinline__ void fma2(unsigned long long& d, unsigned long long a, unsigned long long b) {
    asm("fma.rn.f32x2 %0, %1, %2, %0;" : "+l"(d) : "l"(a), "l"(b));
}

// ---------------- graph preprocessing ----------------
__global__ void hist_kernel(const int* __restrict__ ei, const int* __restrict__ et) {
    int e = blockIdx.x * blockDim.x + threadIdx.x;
    if (e < EE) {
        int dst = ei[EE + e];
        int r = et[e];
        atomicAdd(&g_cnt[dst * RR + r], 1);
    }
}

// single-block scan over node degrees (sum of 8 relation counts per node)
__global__ void scan_kernel() {
    __shared__ int sh[1024];
    __shared__ int s_carry;
    int tid = threadIdx.x;
    if (tid == 0) { s_carry = 0; g_rowptr[0] = 0; }
    __syncthreads();
    for (int base = 0; base < NN; base += 1024) {
        int i = base + tid;
        int v = 0;
        if (i < NN) {
            #pragma unroll
            for (int r = 0; r < RR; r++) v += g_cnt[i * RR + r];
        }
        sh[tid] = v;
        __syncthreads();
        for (int off = 1; off < 1024; off <<= 1) {
            int t = (tid >= off) ? sh[tid - off] : 0;
            __syncthreads();
            sh[tid] += t;
            __syncthreads();
        }
        int incl = sh[tid];
        int c = s_carry;
        if (i < NN) g_rowptr[i + 1] = c + incl;
        __syncthreads();
        if (tid == 0) s_carry = c + sh[1023];
        __syncthreads();
    }
}

// per-node: expand node offset into per-(node,relation) segment starts + invc
__global__ void expand_kernel() {
    int i = blockIdx.x * blockDim.x + threadIdx.x;
    if (i < NN) {
        int c = g_rowptr[i];
        #pragma unroll
        for (int r = 0; r < RR; r++) {
            int cv = g_cnt[i * RR + r];
            g_beg[i * RR + r] = c;
            g_cur[i * RR + r] = c;
            g_invc[i * RR + r] = 1.0f / (float)(cv > 0 ? cv : 1);
            c += cv;
        }
    }
}

__global__ void scatter_kernel(const int* __restrict__ ei, const int* __restrict__ et) {
    int e = blockIdx.x * blockDim.x + threadIdx.x;
    if (e < EE) {
        int comb = ei[EE + e] * RR + et[e];
        int pos = atomicAdd(&g_cur[comb], 1);
        g_ep[pos] = ei[e];
    }
}

// ---------------- fused aggregate+GEMM layer kernel ----------------
// out[i] = relu?( sum_r (mean_{j in N_r(i)} X[j]) @ W_r  +  X[i] @ root + bias )
__global__ __launch_bounds__(512, 1) void fused_kernel(
    const float* __restrict__ X, const float* __restrict__ W,
    const float* __restrict__ root, const float* __restrict__ bias,
    float* __restrict__ out, int do_relu)
{
    extern __shared__ float sm[];
    float* s   = sm;               // [MT][SROW] aggregated tile
    float* Bsp = sm + MT * SROW;   // [64][128][2]  k-pair interleaved weights

    int tid  = threadIdx.x;
    int wid  = tid >> 5;
    int lane = tid & 31;
    int m0   = blockIdx.x * MT;

    // acc[row i][col j]: f32x2 with .lo = even-k partial, .hi = odd-k partial
    unsigned long long acc[8][4];
    #pragma unroll
    for (int i = 0; i < 8; i++)
        #pragma unroll
        for (int j = 0; j < 4; j++) acc[i][j] = 0ULL;

    for (int rel = 0; rel <= RR; rel++) {
        const float* Wp = (rel < RR) ? (W + (size_t)rel * HH * HH) : root;

        // --- stage weights as k-pair interleaved: Bsp[k2*256 + col*2 + {0,1}] ---
        for (int idx = tid; idx < 64 * 32; idx += 512) {
            int k2 = idx >> 5;
            int cq = (idx & 31) * 4;
            float4 w0 = *(const float4*)(Wp + (size_t)(2 * k2) * HH + cq);
            float4 w1 = *(const float4*)(Wp + (size_t)(2 * k2 + 1) * HH + cq);
            unsigned long long* d = (unsigned long long*)(Bsp + k2 * 256 + cq * 2);
            d[0] = pk2(w0.x, w1.x);
            d[1] = pk2(w0.y, w1.y);
            d[2] = pk2(w0.z, w1.z);
            d[3] = pk2(w0.w, w1.w);
        }

        // --- gather/average neighbors into s tile (warp per row) ---
        for (int row = wid; row < MT; row += 16) {
            int gm = m0 + row;
            float4 a = make_float4(0.f, 0.f, 0.f, 0.f);
            if (gm < NN) {
                if (rel == RR) {
                    a = ((const float4*)(X + (size_t)gm * HH))[lane];
                } else {
                    int comb = gm * RR + rel;
                    int b = g_beg[comb];
                    int c = g_cnt[comb];
                    for (int e = b; e < b + c; e++) {
                        int src = g_ep[e];
                        float4 v = ((const float4*)(X + (size_t)src * HH))[lane];
                        a.x += v.x; a.y += v.y; a.z += v.z; a.w += v.w;
                    }
                    float w = g_invc[comb];
                    a.x *= w; a.y *= w; a.z *= w; a.w *= w;
                }
            }
            *(float4*)(s + row * SROW + 4 * lane) = a;
        }
        __syncthreads();

        // --- GEMM accumulate: rows tr..tr+7 (warp-uniform => LDS broadcast),
        //     cols lane + 32j (contiguous LDS64 on Bsp) ---
        int tr = wid * 8;
        for (int k4 = 0; k4 < 32; k4++) {
            const unsigned long long* bp0 = (const unsigned long long*)(Bsp + (2 * k4) * 256);
            const unsigned long long* bp1 = (const unsigned long long*)(Bsp + (2 * k4 + 1) * 256);
            unsigned long long b00 = bp0[lane];
            unsigned long long b01 = bp0[lane + 32];
            unsigned long long b02 = bp0[lane + 64];
            unsigned long long b03 = bp0[lane + 96];
            unsigned long long b10 = bp1[lane];
            unsigned long long b11 = bp1[lane + 32];
            unsigned long long b12 = bp1[lane + 64];
            unsigned long long b13 = bp1[lane + 96];
            #pragma unroll
            for (int i = 0; i < 8; i++) {
                ulonglong2 av = *(const ulonglong2*)(s + (tr + i) * SROW + 4 * k4);
                fma2(acc[i][0], av.x, b00);
                fma2(acc[i][1], av.x, b01);
                fma2(acc[i][2], av.x, b02);
                fma2(acc[i][3], av.x, b03);
                fma2(acc[i][0], av.y, b10);
                fma2(acc[i][1], av.y, b11);
                fma2(acc[i][2], av.y, b12);
                fma2(acc[i][3], av.y, b13);
            }
        }
        __syncthreads();
    }

    // --- epilogue: combine k-split lanes, add bias, relu, store ---
    int tr = wid * 8;
    #pragma unroll
    for (int i = 0; i < 8; i++) {
        int gm = m0 + tr + i;
        if (gm < NN) {
            #pragma unroll
            for (int j = 0; j < 4; j++) {
                int col = lane + 32 * j;
                float lo, hi;
                upk2(acc[i][j], lo, hi);
                float o = lo + hi + bias[col];
                if (do_relu) o = fmaxf(o, 0.f);
                out[(size_t)gm * HH + col] = o;
            }
        }
    }
}

// ---------------- column sums of final layer output ----------------
__global__ void mean_kernel(const float* __restrict__ X, float* __restrict__ usum) {
    __shared__ float sh[256];
    int tid = threadIdx.x;
    int col = tid & 127;
    int half = tid >> 7;
    int rowsPer = (NN + gridDim.x - 1) / gridDim.x;
    int r0 = blockIdx.x * rowsPer;
    int r1 = min(NN, r0 + rowsPer);
    float local = 0.f;
    for (int r = r0 + half; r < r1; r += 2)
        local += X[(size_t)r * HH + col];
    sh[tid] = local;
    __syncthreads();
    if (tid < 128) atomicAdd(&usum[col], sh[tid] + sh[tid + 128]);
}

// ---------------- final MLP head ----------------
__global__ void fcl_kernel(const float* __restrict__ fc1w, const float* __restrict__ fc1b,
                           const float* __restrict__ fc2w, const float* __restrict__ fc2b,
                           float* __restrict__ out) {
    __shared__ float h[2 * HH];
    __shared__ float red[HH];
    int tid = threadIdx.x;
    if (tid < 2 * HH) h[tid] = g_u[tid] * (1.0f / (float)NN);
    __syncthreads();
    if (tid < HH) {
        float y = fc1b[tid];
        for (int k = 0; k < 2 * HH; k++) y += h[k] * fc1w[k * HH + tid];
        y = fmaxf(y, 0.f);
        red[tid] = y * fc2w[tid];
    }
    __syncthreads();
    for (int off = 64; off > 0; off >>= 1) {
        if (tid < off) red[tid] += red[tid + off];
        __syncthreads();
    }
    if (tid == 0) out[0] = red[0] + fc2b[0];
}

// ---------------- host orchestration ----------------
extern "C" void kernel_launch(void* const* d_in, const int* in_sizes, int n_in,
                              void* d_out, int out_size) {
    const float* x1  = (const float*)d_in[0];
    const int*   ei1 = (const int*)d_in[1];
    const int*   et1 = (const int*)d_in[2];
    const float* x2  = (const float*)d_in[3];
    const int*   ei2 = (const int*)d_in[4];
    const int*   et2 = (const int*)d_in[5];
    const float* Wl[3]    = {(const float*)d_in[6],  (const float*)d_in[9],  (const float*)d_in[12]};
    const float* rootl[3] = {(const float*)d_in[7],  (const float*)d_in[10], (const float*)d_in[13]};
    const float* biasl[3] = {(const float*)d_in[8],  (const float*)d_in[11], (const float*)d_in[14]};
    const float* fc1w = (const float*)d_in[15];
    const float* fc1b = (const float*)d_in[16];
    const float* fc2w = (const float*)d_in[17];
    const float* fc2b = (const float*)d_in[18];

    static int smem_set = 0;
    if (!smem_set) {
        cudaFuncSetAttribute(fused_kernel, cudaFuncAttributeMaxDynamicSharedMemorySize, SMEM_BYTES);
        smem_set = 1;
    }

    void *cnt_p, *u_p, *hA_p, *hB_p;
    cudaGetSymbolAddress(&cnt_p, g_cnt);
    cudaGetSymbolAddress(&u_p, g_u);
    cudaGetSymbolAddress(&hA_p, g_hA);
    cudaGetSymbolAddress(&hB_p, g_hB);
    float* hA = (float*)hA_p;
    float* hB = (float*)hB_p;
    float* u  = (float*)u_p;

    cudaMemsetAsync(u_p, 0, 2 * HH * sizeof(float));

    const float* xs[2]  = {x1, x2};
    const int*   eis[2] = {ei1, ei2};
    const int*   ets[2] = {et1, et2};

    for (int g = 0; g < 2; g++) {
        cudaMemsetAsync(cnt_p, 0, NN * RR * sizeof(int));
        hist_kernel<<<(EE + 255) / 256, 256>>>(eis[g], ets[g]);
        scan_kernel<<<1, 1024>>>();
        expand_kernel<<<(NN + 255) / 256, 256>>>();
        scatter_kernel<<<(EE + 255) / 256, 256>>>(eis[g], ets[g]);

        const float* Xin = xs[g];
        for (int l = 0; l < 3; l++) {
            float* outbuf = (l == 1) ? hB : hA;   // l0->hA, l1->hB, l2->hA
            fused_kernel<<<NBLK, 512, SMEM_BYTES>>>(Xin, Wl[l], rootl[l], biasl[l],
                                                    outbuf, (l < 2) ? 1 : 0);
            Xin = outbuf;
        }
        mean_kernel<<<128, 256>>>(Xin, u + g * HH);
    }

    fcl_kernel<<<1, 256>>>(fc1w, fc1b, fc2w, fc2b, (float*)d_out);
}